// round 15
// baseline (speedup 1.0000x reference)
#include <cuda_runtime.h>

// QuConvSXZ: 12-qubit pairwise-gate circuit + partial trace (REAL part out).
//
//   phi = U psi;  out[i,j] = Re( sum_t phi[t*64+i] * conj(phi[t*64+j]) )
// Gates on traced (leading) qubits cancel by unitarity; only pairs 3,4,5 act,
// on base-4 digits (5,4),(3,2),(1,0) of the kept index; each gate is
// diag+antidiag {a,b,d,e} (analytic form silicon-validated R1==R2).
//
// R14 = R13 evolution/layout (best) + 128-CTA grid (1 row/CTA, 128/148 SMs
// vs 64 before — active SMSPs were issue-saturated) + 32-way t-split trace
// (loop 2) + 4-accumulator reduce (breaks the serial FADD chain).
//
// phi slots: (o0,o1) -> slot sub, (o2,o3) -> slot sub+16 (conflict-free STS);
// j-permutation: slot s<16: j = 4s+{0,1}; s>=16: j = 4(s-16)+{2,3}.

#define NTHREADS 1024

typedef float2 cplx;

__global__ __launch_bounds__(NTHREADS, 1)
void quconv_kernel(const float* __restrict__ x,
                   const float* __restrict__ w,
                   float* __restrict__ out)
{
    __shared__ float4 psi4[2048];      // 32 KB phi (permuted slots)
    __shared__ float  part[32][64];    // trace partials [tq][slotpos] (8 KB)

    const int tid   = threadIdx.x;
    const int batch = blockIdx.y;
    const int irow  = blockIdx.x;      // 0..63: output row i
    const int lane  = tid & 31;
    const int warp  = tid >> 5;
    const unsigned FULL = 0xffffffffu;

    // ---- issue x load immediately (overlaps per-warp gate build) ----
    const float4 xv = ((const float4*)(x + batch * 4096))[tid];

    // ---- per-warp gate build: lane l in {0,1,2} builds pair (3+l) ----
    float gax = 0.f, gay = 0.f, gbx = 0.f, gby = 0.f;
    float gdx = 0.f, gdy = 0.f, gex = 0.f, gey = 0.f;
    if (lane < 3) {
        const float WMUL_H = 0.31622776601683794f;  // sqrt(2/5)/2
        const int idx = 54 + 6 * lane;              // pairs 3,4,5
        float t1 = w[idx]     * WMUL_H;
        float t2 = w[idx + 1] * WMUL_H;
        float t3 = w[idx + 2] * WMUL_H;
        float cu, su, cv, sv, c3, s3;
        __sincosf(t1 - t2, &su, &cu);
        __sincosf(t1 + t2, &sv, &cv);
        __sincosf(t3, &s3, &c3);
        const float sb = -su;
        gax =  c3 * cu;  gay = -s3 * cu;   // a
        gbx =  s3 * sb;  gby =  c3 * sb;   // b
        gdx =  c3 * cv;  gdy =  s3 * cv;   // d
        gex =  s3 * sv;  gey = -c3 * sv;   // e
    }

    // ---- register evolution (identical to R11/R13) ----
    const int s1v = lane & 3;          // digit (3,2)
    const int s2v = (lane >> 2) & 3;   // digit (5,4)
    const int row = 2 * warp + (lane >> 4);
    const int sub = lane & 15;

    cplx o0, o1, o2, o3;
    {   // stage A: pair 5 (lane 2), digit (1,0) intra-thread, REAL input
        const float ax = __shfl_sync(FULL, gax, 2), ay = __shfl_sync(FULL, gay, 2);
        const float bx = __shfl_sync(FULL, gbx, 2), by = __shfl_sync(FULL, gby, 2);
        const float dx = __shfl_sync(FULL, gdx, 2), dy = __shfl_sync(FULL, gdy, 2);
        const float ex = __shfl_sync(FULL, gex, 2), ey = __shfl_sync(FULL, gey, 2);
        o0.x = fmaf(ax, xv.x, bx * xv.w);  o0.y = fmaf(ay, xv.x, by * xv.w);
        o3.x = fmaf(ax, xv.w, bx * xv.x);  o3.y = fmaf(ay, xv.w, by * xv.x);
        o1.x = fmaf(dx, xv.y, ex * xv.z);  o1.y = fmaf(dy, xv.y, ey * xv.z);
        o2.x = fmaf(dx, xv.z, ex * xv.y);  o2.y = fmaf(dy, xv.z, ey * xv.y);
    }
    {   // stage B: pair 4 (lane 1), digit s1v, partner lane^3
        const float ax = __shfl_sync(FULL, gax, 1), ay = __shfl_sync(FULL, gay, 1);
        const float bx = __shfl_sync(FULL, gbx, 1), by = __shfl_sync(FULL, gby, 1);
        const float dx = __shfl_sync(FULL, gdx, 1), dy = __shfl_sync(FULL, gdy, 1);
        const float ex = __shfl_sync(FULL, gex, 1), ey = __shfl_sync(FULL, gey, 1);
        const bool outer = (s1v == 0) || (s1v == 3);
        const float Dx = outer ? ax : dx, Dy = outer ? ay : dy;
        const float Ax = outer ? bx : ex, Ay = outer ? by : ey;
        float p0x = __shfl_xor_sync(FULL, o0.x, 3), p0y = __shfl_xor_sync(FULL, o0.y, 3);
        float p1x = __shfl_xor_sync(FULL, o1.x, 3), p1y = __shfl_xor_sync(FULL, o1.y, 3);
        float p2x = __shfl_xor_sync(FULL, o2.x, 3), p2y = __shfl_xor_sync(FULL, o2.y, 3);
        float p3x = __shfl_xor_sync(FULL, o3.x, 3), p3y = __shfl_xor_sync(FULL, o3.y, 3);
        cplx n0, n1, n2, n3;
        n0.x = fmaf(Dx,o0.x, fmaf(-Dy,o0.y, fmaf(Ax,p0x, -Ay*p0y)));
        n0.y = fmaf(Dx,o0.y, fmaf( Dy,o0.x, fmaf(Ax,p0y,  Ay*p0x)));
        n1.x = fmaf(Dx,o1.x, fmaf(-Dy,o1.y, fmaf(Ax,p1x, -Ay*p1y)));
        n1.y = fmaf(Dx,o1.y, fmaf( Dy,o1.x, fmaf(Ax,p1y,  Ay*p1x)));
        n2.x = fmaf(Dx,o2.x, fmaf(-Dy,o2.y, fmaf(Ax,p2x, -Ay*p2y)));
        n2.y = fmaf(Dx,o2.y, fmaf( Dy,o2.x, fmaf(Ax,p2y,  Ay*p2x)));
        n3.x = fmaf(Dx,o3.x, fmaf(-Dy,o3.y, fmaf(Ax,p3x, -Ay*p3y)));
        n3.y = fmaf(Dx,o3.y, fmaf( Dy,o3.x, fmaf(Ax,p3y,  Ay*p3x)));
        o0 = n0; o1 = n1; o2 = n2; o3 = n3;
    }
    {   // stage C: pair 3 (lane 0), digit s2v, partner lane^12
        const float ax = __shfl_sync(FULL, gax, 0), ay = __shfl_sync(FULL, gay, 0);
        const float bx = __shfl_sync(FULL, gbx, 0), by = __shfl_sync(FULL, gby, 0);
        const float dx = __shfl_sync(FULL, gdx, 0), dy = __shfl_sync(FULL, gdy, 0);
        const float ex = __shfl_sync(FULL, gex, 0), ey = __shfl_sync(FULL, gey, 0);
        const bool outer = (s2v == 0) || (s2v == 3);
        const float Dx = outer ? ax : dx, Dy = outer ? ay : dy;
        const float Ax = outer ? bx : ex, Ay = outer ? by : ey;
        float p0x = __shfl_xor_sync(FULL, o0.x, 12), p0y = __shfl_xor_sync(FULL, o0.y, 12);
        float p1x = __shfl_xor_sync(FULL, o1.x, 12), p1y = __shfl_xor_sync(FULL, o1.y, 12);
        float p2x = __shfl_xor_sync(FULL, o2.x, 12), p2y = __shfl_xor_sync(FULL, o2.y, 12);
        float p3x = __shfl_xor_sync(FULL, o3.x, 12), p3y = __shfl_xor_sync(FULL, o3.y, 12);
        cplx n0, n1, n2, n3;
        n0.x = fmaf(Dx,o0.x, fmaf(-Dy,o0.y, fmaf(Ax,p0x, -Ay*p0y)));
        n0.y = fmaf(Dx,o0.y, fmaf( Dy,o0.x, fmaf(Ax,p0y,  Ay*p0x)));
        n1.x = fmaf(Dx,o1.x, fmaf(-Dy,o1.y, fmaf(Ax,p1x, -Ay*p1y)));
        n1.y = fmaf(Dx,o1.y, fmaf( Dy,o1.x, fmaf(Ax,p1y,  Ay*p1x)));
        n2.x = fmaf(Dx,o2.x, fmaf(-Dy,o2.y, fmaf(Ax,p2x, -Ay*p2y)));
        n2.y = fmaf(Dx,o2.y, fmaf( Dy,o2.x, fmaf(Ax,p2y,  Ay*p2x)));
        n3.x = fmaf(Dx,o3.x, fmaf(-Dy,o3.y, fmaf(Ax,p3x, -Ay*p3y)));
        n3.y = fmaf(Dx,o3.y, fmaf( Dy,o3.x, fmaf(Ax,p3y,  Ay*p3x)));
        o0 = n0; o1 = n1; o2 = n2; o3 = n3;
    }

    // ---- write phi, conflict-free permuted slots ----
    psi4[row * 32 + sub]      = make_float4(o0.x, o0.y, o1.x, o1.y);
    psi4[row * 32 + sub + 16] = make_float4(o2.x, o2.y, o3.x, o3.y);
    __syncthreads();

    // ---- trace (Re only): 32-way t-split; thread = (slot jj, tq) ----
    {
        const int jj = tid & 31;            // slot index
        const int tq = tid >> 5;            // t-chunk 0..31 (warp-uniform)
        // vi slot/half for column irow under the permuted layout
        const int s_i = (irow & 2) ? (16 + (irow >> 2)) : (irow >> 2);
        const int c_i = irow & 1;
        float a0 = 0.f, a1 = 0.f, b0 = 0.f, b1 = 0.f;
        {
            const int t = tq * 2;
            float2 vi = ((const float2*)&psi4[t * 32 + s_i])[c_i];  // broadcast
            float4 vj = psi4[t * 32 + jj];                          // conflict-free
            a0 = fmaf(vi.x, vj.x, vi.y * vj.y);
            a1 = fmaf(vi.x, vj.z, vi.y * vj.w);
        }
        {
            const int t = tq * 2 + 1;
            float2 vi = ((const float2*)&psi4[t * 32 + s_i])[c_i];
            float4 vj = psi4[t * 32 + jj];
            b0 = fmaf(vi.x, vj.x, vi.y * vj.y);
            b1 = fmaf(vi.x, vj.z, vi.y * vj.w);
        }
        ((float2*)&part[tq][0])[jj] = make_float2(a0 + b0, a1 + b1);
    }
    __syncthreads();

    // ---- reduce: 64 threads, 4 independent accumulator chains ----
    if (tid < 64) {
        const int p = tid;                 // slot-position within row
        float s0 = 0.f, s1 = 0.f, s2 = 0.f, s3 = 0.f;
        #pragma unroll
        for (int tq = 0; tq < 8; ++tq) {
            s0 += part[4 * tq    ][p];
            s1 += part[4 * tq + 1][p];
            s2 += part[4 * tq + 2][p];
            s3 += part[4 * tq + 3][p];
        }
        const int slot = p >> 1, c = p & 1;
        const int j = (slot < 16) ? (4 * slot + c) : (4 * (slot - 16) + 2 + c);
        out[batch * 4096 + irow * 64 + j] = (s0 + s1) + (s2 + s3);
    }
}

extern "C" void kernel_launch(void* const* d_in, const int* in_sizes, int n_in,
                              void* d_out, int out_size) {
    // Rank-by-size binding: largest -> x, second largest -> weight.
    int ix = 0, iw = 0;
    for (int i = 1; i < n_in; ++i) if (in_sizes[i] > in_sizes[ix]) ix = i;
    iw = (ix == 0 && n_in > 1) ? 1 : 0;
    for (int i = 0; i < n_in; ++i)
        if (i != ix && in_sizes[i] > in_sizes[iw]) iw = i;
    const float* x = (const float*)d_in[ix];
    const float* w = (const float*)d_in[iw];

    dim3 grid(64, 2);   // 64 rows x 2 batches = 128 CTAs (one wave, 128/148 SMs)
    quconv_kernel<<<grid, NTHREADS>>>(x, w, (float*)d_out);
}